// round 9
// baseline (speedup 1.0000x reference)
#include <cuda_runtime.h>

// ---------------- problem constants -----------------------------------------
#define B_    16
#define M_    32768
#define K_    85
#define KP    96            // kernel points padded to 8 pairs x 12
#define NF_   64
#define DO_   16
#define NCH   128           // chunks per batch (kernel A)
#define CHPT  (M_ / NCH)    // 256 points per chunk
#define PTS   32            // points per smem tile in kernel A
#define NTILE (CHPT / PTS)  // 8
#define QROW  100           // padded qd row (words)
#define PPD   512           // points per kD block (4 per thread, 128 threads)
#define OUTW  (NF_ + DO_)   // 80
#define LOG2E 1.4426950408889634f

typedef unsigned long long ull;
typedef unsigned int u32;

// ---------------- scratch (device globals: sanctioned no-alloc path) --------
__device__ __align__(16) float g_qf_partial[B_ * NCH * KP * NF_];   // ~50 MB
__device__ __align__(16) float g_P[B_ * K_ * DO_];

__device__ __forceinline__ float ex2f(float x) {
    float y; asm("ex2.approx.ftz.f32 %0, %1;" : "=f"(y) : "f"(x)); return y;
}
// packed fp32x2 FMA (FFMA2; ptxas never auto-fuses — PTX only)
__device__ __forceinline__ void fma2(ull& d, ull a, ull b) {
    asm("fma.rn.f32x2 %0, %1, %2, %0;" : "+l"(d) : "l"(a), "l"(b));
}
__device__ __forceinline__ ull splat2(float x) {
    ull d; u32 u = __float_as_uint(x);
    asm("mov.b64 %0, {%1, %1};" : "=l"(d) : "r"(u)); return d;
}
__device__ __forceinline__ u32 smem_u32(const void* p) {
    u32 a; asm("{.reg .u64 t; cvta.to.shared.u64 t, %1; cvt.u32.u64 %0, t;}"
               : "=r"(a) : "l"(p)); return a;
}
__device__ __forceinline__ void cp16(u32 saddr, const void* g) {
    asm volatile("cp.async.cg.shared.global [%0], [%1], 16;"
                 :: "r"(saddr), "l"(g) : "memory");
}
__device__ __forceinline__ void cp_commit() {
    asm volatile("cp.async.commit_group;" ::: "memory");
}
__device__ __forceinline__ void cp_wait_all() {
    asm volatile("cp.async.wait_group 0;" ::: "memory");
}

// ===========================================================================
// Kernel A: partial QF[b,ch,k,f] = sum_{p in chunk} qd(p,k) * F[p,f]
// 64 threads. Phase 2: thread t<44 owns k-pair (2t,2t+1); its 10 folded
// constants live in REGISTERS across all tiles (no per-tile smem reloads).
// Phase 3: thread (kg,fg) in 8x8 owns 6 k-PAIRS x 8 f (f32x2 over k-pairs).
// Double-buffered cp.async F/X tiles; s_qd single-buffered (sync-ordered).
// (omegaF applied later, in kB.)
// ===========================================================================
__global__ __launch_bounds__(64, 6)
void kA(const float* __restrict__ X, const float* __restrict__ F,
        const float* __restrict__ QX, const float* __restrict__ omD)
{
    __shared__ __align__(16) float4 s_cst[KP];        // staging for reg constants
    __shared__ float s_c[KP];
    __shared__ __align__(16) float s_f[2][PTS][NF_];  // raw F tiles (cp.async)
    __shared__ __align__(16) float s_xr[2][PTS * 3];  // raw X tiles (cp.async)
    __shared__ __align__(16) float s_qd[PTS][QROW];   // single-buffered qd

    const int tid = threadIdx.x;
    const int b   = blockIdx.y;
    const int ch  = blockIdx.x;
    const long base = (long)b * M_ + (long)ch * CHPT;

    // folded per-k constants: arg = c - s*x2 + qx'.x
    for (int e = tid; e < KP; e += 64) {
        float qx = 0.f, qy = 0.f, qz = 0.f, sk = 0.f, ck = -1e30f; // pad -> qd=0
        if (e < K_) {
            qx = QX[e * 3 + 0]; qy = QX[e * 3 + 1]; qz = QX[e * 3 + 2];
            float om = omD[e];
            float inv = 1.0f / (om * om);
            float q2 = qx * qx + qy * qy + qz * qz;
            sk = inv * LOG2E; ck = -q2 * inv * LOG2E;
            float tt = 2.0f * inv * LOG2E;
            qx *= tt; qy *= tt; qz *= tt;
        }
        s_cst[e] = make_float4(qx, qy, qz, sk);
        s_c[e]   = ck;
    }
    // zero qd rows 88..95 once (phase 2 writes only 0..87; never rewritten)
    for (int e = tid; e < PTS * 8; e += 64)
        s_qd[e >> 3][88 + (e & 7)] = 0.f;

    // ---- issue tile 0 ----
    {
        const float* gf = F + base * NF_;
        u32 sf = smem_u32(&s_f[0][0][0]);
#pragma unroll
        for (int i = 0; i < 8; i++) {
            int e = tid + i * 64;
            cp16(sf + e * 16, gf + e * 4);
        }
        if (tid < 24)
            cp16(smem_u32(&s_xr[0][0]) + tid * 16, X + base * 3 + tid * 4);
        cp_commit();
    }

    __syncthreads();   // s_cst/s_c ready for register caching

    // ---- register-cache this thread's k-pair constants (tid < 44) ----
    float4 rc0 = make_float4(0.f, 0.f, 0.f, 0.f), rc1 = rc0;
    float rcc0 = -1e30f, rcc1 = -1e30f;
    if (tid < 44) {
        rc0 = s_cst[2 * tid];     rc1 = s_cst[2 * tid + 1];
        rcc0 = s_c[2 * tid];      rcc1 = s_c[2 * tid + 1];
    }

    const int kg = tid >> 3;   // kpair-group: k rows kg*12 .. kg*12+11
    const int fg = tid & 7;    // f cols fg*8 .. fg*8+7

    ull acc[6][8];             // [kpair][f] : lanes = (k0,k1)
#pragma unroll
    for (int i = 0; i < 6; i++)
#pragma unroll
        for (int j = 0; j < 8; j++) acc[i][j] = 0ull;

    for (int t = 0; t < NTILE; t++) {
        const int bf = t & 1;
        cp_wait_all();
        __syncthreads();        // tile t F/X visible; phase3(t-1) complete

        // ---- phase 2: k-slice qd generation (constants in registers) ----
        if (tid < 44) {
            float* dst = &s_qd[0][2 * tid];
#pragma unroll 4
            for (int p = 0; p < PTS; p++) {
                float x = s_xr[bf][p * 3 + 0];      // broadcast LDS.32
                float y = s_xr[bf][p * 3 + 1];
                float z = s_xr[bf][p * 3 + 2];
                float x2 = fmaf(z, z, fmaf(y, y, x * x));
                float a0 = fmaf(rc0.z, z, fmaf(rc0.y, y,
                           fmaf(rc0.x, x, fmaf(-rc0.w, x2, rcc0))));
                float a1 = fmaf(rc1.z, z, fmaf(rc1.y, y,
                           fmaf(rc1.x, x, fmaf(-rc1.w, x2, rcc1))));
                float2 w; w.x = ex2f(a0); w.y = ex2f(a1);
                *(float2*)dst = w;                  // contiguous across warp
                dst += QROW;
            }
        }

        // ---- prefetch tile t+1 into the other F/X buffer ----
        if (t + 1 < NTILE) {
            const long p0n = base + (long)(t + 1) * PTS;
            const float* gf = F + p0n * NF_;
            u32 sf = smem_u32(&s_f[1 - bf][0][0]);
#pragma unroll
            for (int i = 0; i < 8; i++) {
                int e = tid + i * 64;
                cp16(sf + e * 16, gf + e * 4);
            }
            if (tid < 24)
                cp16(smem_u32(&s_xr[1 - bf][0]) + tid * 16, X + p0n * 3 + tid * 4);
            cp_commit();
        }
        __syncthreads();        // qd(t) visible

        // ---- phase 3: rank-PTS update, k-pair-packed f32x2 ----
#pragma unroll 2
        for (int p = 0; p < PTS; ++p) {
            const ulonglong2* ap = (const ulonglong2*)&s_qd[p][kg * 12];
            ulonglong2 A0 = ap[0], A1 = ap[1], A2 = ap[2];  // 6 qd pairs
            const float4* bp = (const float4*)&s_f[bf][p][fg * 8];
            float4 b0 = bp[0], b1 = bp[1];
            ull B0 = splat2(b0.x), B1 = splat2(b0.y), B2 = splat2(b0.z), B3 = splat2(b0.w);
            ull B4 = splat2(b1.x), B5 = splat2(b1.y), B6 = splat2(b1.z), B7 = splat2(b1.w);
            fma2(acc[0][0], A0.x, B0); fma2(acc[0][1], A0.x, B1);
            fma2(acc[0][2], A0.x, B2); fma2(acc[0][3], A0.x, B3);
            fma2(acc[0][4], A0.x, B4); fma2(acc[0][5], A0.x, B5);
            fma2(acc[0][6], A0.x, B6); fma2(acc[0][7], A0.x, B7);
            fma2(acc[1][0], A0.y, B0); fma2(acc[1][1], A0.y, B1);
            fma2(acc[1][2], A0.y, B2); fma2(acc[1][3], A0.y, B3);
            fma2(acc[1][4], A0.y, B4); fma2(acc[1][5], A0.y, B5);
            fma2(acc[1][6], A0.y, B6); fma2(acc[1][7], A0.y, B7);
            fma2(acc[2][0], A1.x, B0); fma2(acc[2][1], A1.x, B1);
            fma2(acc[2][2], A1.x, B2); fma2(acc[2][3], A1.x, B3);
            fma2(acc[2][4], A1.x, B4); fma2(acc[2][5], A1.x, B5);
            fma2(acc[2][6], A1.x, B6); fma2(acc[2][7], A1.x, B7);
            fma2(acc[3][0], A1.y, B0); fma2(acc[3][1], A1.y, B1);
            fma2(acc[3][2], A1.y, B2); fma2(acc[3][3], A1.y, B3);
            fma2(acc[3][4], A1.y, B4); fma2(acc[3][5], A1.y, B5);
            fma2(acc[3][6], A1.y, B6); fma2(acc[3][7], A1.y, B7);
            fma2(acc[4][0], A2.x, B0); fma2(acc[4][1], A2.x, B1);
            fma2(acc[4][2], A2.x, B2); fma2(acc[4][3], A2.x, B3);
            fma2(acc[4][4], A2.x, B4); fma2(acc[4][5], A2.x, B5);
            fma2(acc[4][6], A2.x, B6); fma2(acc[4][7], A2.x, B7);
            fma2(acc[5][0], A2.y, B0); fma2(acc[5][1], A2.y, B1);
            fma2(acc[5][2], A2.y, B2); fma2(acc[5][3], A2.y, B3);
            fma2(acc[5][4], A2.y, B4); fma2(acc[5][5], A2.y, B5);
            fma2(acc[5][6], A2.y, B6); fma2(acc[5][7], A2.y, B7);
        }
        // no trailing sync: next iteration's sync orders qd/F buffer reuse
    }

    // ---- epilogue: unpack k-pairs, write 96x64 partial (float4) ----
    const int part = b * NCH + ch;
#pragma unroll
    for (int i = 0; i < 6; i++) {
        int k0 = kg * 12 + 2 * i;
        float2 v0 = *(float2*)&acc[i][0], v1 = *(float2*)&acc[i][1];
        float2 v2 = *(float2*)&acc[i][2], v3 = *(float2*)&acc[i][3];
        float2 v4 = *(float2*)&acc[i][4], v5 = *(float2*)&acc[i][5];
        float2 v6 = *(float2*)&acc[i][6], v7 = *(float2*)&acc[i][7];
        float* d0 = &g_qf_partial[((long)part * KP + k0) * NF_ + fg * 8];
        *(float4*)(d0)       = make_float4(v0.x, v1.x, v2.x, v3.x);
        *(float4*)(d0 + 4)   = make_float4(v4.x, v5.x, v6.x, v7.x);
        float* d1 = d0 + NF_;
        *(float4*)(d1)       = make_float4(v0.y, v1.y, v2.y, v3.y);
        *(float4*)(d1 + 4)   = make_float4(v4.y, v5.y, v6.y, v7.y);
    }
}

// ===========================================================================
// Kernel B: reduce partials over chunks, apply omegaF, project through QW
// -> P[b,k,0:16].  grid (K_, B_), 64 threads.
// ===========================================================================
__global__ __launch_bounds__(64)
void kB(const float* __restrict__ QW, const float* __restrict__ omF)
{
    const int k = blockIdx.x, b = blockIdx.y, f = threadIdx.x;
    const float* p = g_qf_partial + ((long)(b * NCH) * KP + k) * NF_ + f;
    float s = 0.f;
#pragma unroll 8
    for (int c = 0; c < NCH; c++) s += p[(long)c * KP * NF_];

    __shared__ float sq[NF_];
    sq[f] = s * omF[f];            // omegaF folded here
    __syncthreads();

    if (f < DO_) {
        float a = 0.f;
#pragma unroll
        for (int j = 0; j < NF_; j++) a = fmaf(sq[j], QW[j * DO_ + f], a);
        g_P[(b * K_ + k) * DO_ + f] = a;
    }
}

// ===========================================================================
// Kernel D: QY[m,:] = sum_k qd(m,k) * P[k,:]; out = concat(F, QY)
// 128 threads, 4 points/thread: P-row LDS amortized 4x.
// ===========================================================================
__global__ __launch_bounds__(128, 3)
void kD(const float* __restrict__ X, const float* __restrict__ F,
        const float* __restrict__ QX, const float* __restrict__ omD,
        float* __restrict__ out)
{
    __shared__ float s_qx0[K_], s_qx1[K_], s_qx2[K_], s_c[K_], s_s[K_];
    __shared__ __align__(16) float s_P[K_][DO_];        // rows 64B
    __shared__ __align__(16) float s_y[PPD][DO_ + 2];   // rows 72B

    const int tid = threadIdx.x;
    const int b   = blockIdx.y;
    const long base = (long)b * M_ + (long)blockIdx.x * PPD;

    if (tid < K_) {
        float qx = QX[tid * 3 + 0], qy = QX[tid * 3 + 1], qz = QX[tid * 3 + 2];
        float om = omD[tid];
        float inv = 1.0f / (om * om);
        float q2 = qx * qx + qy * qy + qz * qz;
        s_s[tid] = inv * LOG2E;
        s_c[tid] = -q2 * inv * LOG2E;
        float t = 2.0f * inv * LOG2E;
        s_qx0[tid] = qx * t; s_qx1[tid] = qy * t; s_qx2[tid] = qz * t;
    }
    for (int e = tid; e < K_ * DO_; e += 128)
        (&s_P[0][0])[e] = g_P[(long)b * K_ * DO_ + e];
    __syncthreads();

    {
        const int p0 = tid * 4;
        const float4* xp = (const float4*)(X + (base + p0) * 3);  // 48B aligned
        float4 u0 = xp[0], u1 = xp[1], u2 = xp[2];
        float xs[4] = {u0.x, u0.w, u1.z, u2.y};
        float ys[4] = {u0.y, u1.x, u1.w, u2.z};
        float zs[4] = {u0.z, u1.y, u2.x, u2.w};
        float x2s[4];
#pragma unroll
        for (int i = 0; i < 4; i++)
            x2s[i] = fmaf(zs[i], zs[i], fmaf(ys[i], ys[i], xs[i] * xs[i]));

        ull acc[4][8];
#pragma unroll
        for (int i = 0; i < 4; i++)
#pragma unroll
            for (int d = 0; d < 8; d++) acc[i][d] = 0ull;

#pragma unroll 5
        for (int k = 0; k < K_; k++) {
            float c0 = s_qx0[k], c1 = s_qx1[k], c2 = s_qx2[k];
            float sk = s_s[k], ck = s_c[k];
            ull q[4];
#pragma unroll
            for (int i = 0; i < 4; i++) {
                float arg = fmaf(c2, zs[i], fmaf(c1, ys[i],
                            fmaf(c0, xs[i], fmaf(-sk, x2s[i], ck))));
                q[i] = splat2(ex2f(arg));
            }
            const ulonglong2* pr = (const ulonglong2*)&s_P[k][0];  // broadcast
            ulonglong2 r0 = pr[0], r1 = pr[1], r2 = pr[2], r3 = pr[3];
#pragma unroll
            for (int i = 0; i < 4; i++) {
                fma2(acc[i][0], q[i], r0.x); fma2(acc[i][1], q[i], r0.y);
                fma2(acc[i][2], q[i], r1.x); fma2(acc[i][3], q[i], r1.y);
                fma2(acc[i][4], q[i], r2.x); fma2(acc[i][5], q[i], r2.y);
                fma2(acc[i][6], q[i], r3.x); fma2(acc[i][7], q[i], r3.y);
            }
        }
#pragma unroll
        for (int i = 0; i < 4; i++)
#pragma unroll
            for (int d = 0; d < 8; d++)
                *(float2*)&s_y[p0 + i][2 * d] = *(float2*)&acc[i][d];
    }
    __syncthreads();

    // cooperative coalesced write: 512 points x 80 floats = 10240 float4
    const float4* f4 = (const float4*)(F + base * NF_);
    float4*       o4 = (float4*)(out + base * OUTW);
#pragma unroll 8
    for (int i = 0; i < (PPD * OUTW / 4) / 128; i++) {   // 80 iterations
        int e  = tid + i * 128;
        int pt = e / (OUTW / 4);
        int c  = e % (OUTW / 4);
        float4 v;
        if (c < NF_ / 4) {
            v = f4[pt * (NF_ / 4) + c];
        } else {
            int d = (c - NF_ / 4) * 4;
            v = make_float4(s_y[pt][d], s_y[pt][d + 1], s_y[pt][d + 2], s_y[pt][d + 3]);
        }
        o4[e] = v;
    }
}

// ===========================================================================
extern "C" void kernel_launch(void* const* d_in, const int* in_sizes, int n_in,
                              void* d_out, int out_size)
{
    const float* X   = (const float*)d_in[0];
    const float* F   = (const float*)d_in[1];
    const float* QX  = (const float*)d_in[2];
    const float* omD = (const float*)d_in[3];
    const float* omF = (const float*)d_in[4];
    const float* QW  = (const float*)d_in[5];
    float* out = (float*)d_out;

    kA<<<dim3(NCH, B_), 64>>>(X, F, QX, omD);
    kB<<<dim3(K_, B_), 64>>>(QW, omF);
    kD<<<dim3(M_ / PPD, B_), 128>>>(X, F, QX, omD, out);
}